// round 1
// baseline (speedup 1.0000x reference)
#include <cuda_runtime.h>
#include <math.h>

#define EPS_F 1.1920928955078125e-07f
#define RED_SLICES 16
#define RED_THREADS 256

// scratch (allocation-free rule): partial sums + final stats
__device__ float g_partials[256 * RED_SLICES * 2];  // [b][slice][{sum,sumsq}]
__device__ float g_stats[512];                      // [b][{mean,rstd}]

// ---------------------------------------------------------------------------
// Kernel 1: per-batch prefix sum & sumsq partials.
// grid = (B, RED_SLICES), block = RED_THREADS
// ---------------------------------------------------------------------------
__global__ void reduce_kernel(const float* __restrict__ data,
                              const int* __restrict__ zero_pos,
                              int C, int L) {
    int b  = blockIdx.x;
    int zp = zero_pos[b];
    const float* base = data + (size_t)b * C * L;

    int total   = C * zp;                       // <= 64*8192 = 524288, fits int
    int gtid    = blockIdx.y * RED_THREADS + threadIdx.x;
    int gstride = gridDim.y * RED_THREADS;

    float s = 0.0f, sq = 0.0f;
    for (int i = gtid; i < total; i += gstride) {
        int c = i / zp;
        int l = i - c * zp;
        float v = base[(size_t)c * L + l];
        s  += v;
        sq += v * v;
    }

    // block reduction
    __shared__ float sh_s[RED_THREADS];
    __shared__ float sh_q[RED_THREADS];
    int tid = threadIdx.x;
    sh_s[tid] = s;
    sh_q[tid] = sq;
    __syncthreads();
    for (int off = RED_THREADS / 2; off >= 32; off >>= 1) {
        if (tid < off) {
            sh_s[tid] += sh_s[tid + off];
            sh_q[tid] += sh_q[tid + off];
        }
        __syncthreads();
    }
    if (tid < 32) {
        float vs = sh_s[tid];
        float vq = sh_q[tid];
        for (int off = 16; off > 0; off >>= 1) {
            vs += __shfl_down_sync(0xFFFFFFFFu, vs, off);
            vq += __shfl_down_sync(0xFFFFFFFFu, vq, off);
        }
        if (tid == 0) {
            int slot = (b * RED_SLICES + blockIdx.y) * 2;
            g_partials[slot + 0] = vs;
            g_partials[slot + 1] = vq;
        }
    }
}

// ---------------------------------------------------------------------------
// Kernel 2: fold partials -> mean, 1/(std+eps). 1 block, B threads.
// ---------------------------------------------------------------------------
__global__ void stats_kernel(const int* __restrict__ zero_pos, int C) {
    int b = threadIdx.x;
    float s = 0.0f, sq = 0.0f;
#pragma unroll
    for (int j = 0; j < RED_SLICES; j++) {
        int slot = (b * RED_SLICES + j) * 2;
        s  += g_partials[slot + 0];
        sq += g_partials[slot + 1];
    }
    float cnt  = (float)C * (float)zero_pos[b];
    float mean = s / cnt;
    float var  = (sq - cnt * mean * mean) / (cnt - 1.0f);
    float stdv = sqrtf(var);
    g_stats[2 * b + 0] = mean;
    g_stats[2 * b + 1] = 1.0f / (stdv + EPS_F);
}

// ---------------------------------------------------------------------------
// Kernel 3: normalize full tensor, float4 vectorized.
// cl4_shift = log2(C*L/4); b = i4 >> cl4_shift
// ---------------------------------------------------------------------------
__global__ void norm_kernel(const float4* __restrict__ data4,
                            float4* __restrict__ out4,
                            int n4, int cl4_shift) {
    int stride = gridDim.x * blockDim.x;
    for (int i = blockIdx.x * blockDim.x + threadIdx.x; i < n4; i += stride) {
        int b = i >> cl4_shift;
        float mean = g_stats[2 * b + 0];
        float rstd = g_stats[2 * b + 1];
        float4 v = data4[i];
        v.x = (v.x - mean) * rstd;
        v.y = (v.y - mean) * rstd;
        v.z = (v.z - mean) * rstd;
        v.w = (v.w - mean) * rstd;
        out4[i] = v;
    }
}

// ---------------------------------------------------------------------------
// Kernel 4: tail outputs — idxes and zero_pos value-cast to float.
// ---------------------------------------------------------------------------
__global__ void tail_kernel(const int* __restrict__ idxes,
                            const int* __restrict__ zero_pos,
                            float* __restrict__ out_tail,
                            int n_idx, int n_zp) {
    int i = blockIdx.x * blockDim.x + threadIdx.x;
    if (i < n_idx) {
        out_tail[i] = (float)idxes[i];
    } else if (i < n_idx + n_zp) {
        out_tail[i] = (float)zero_pos[i - n_idx];
    }
}

extern "C" void kernel_launch(void* const* d_in, const int* in_sizes, int n_in,
                              void* d_out, int out_size) {
    const float* data     = (const float*)d_in[0];
    const int*   idxes    = (const int*)d_in[1];
    const int*   zero_pos = (const int*)d_in[2];
    float*       out      = (float*)d_out;

    int n_data = in_sizes[0];            // B*C*L
    int n_idx  = in_sizes[1];            // B*L
    int B      = in_sizes[2];            // 64
    int CL     = n_data / B;             // C*L = 524288
    int L      = n_idx / B;              // 8192
    int C      = CL / L;                 // 64

    // 1) partial reductions over prefixes
    dim3 g1(B, RED_SLICES);
    reduce_kernel<<<g1, RED_THREADS>>>(data, zero_pos, C, L);

    // 2) stats
    stats_kernel<<<1, B>>>(zero_pos, C);

    // 3) normalize (float4)
    int n4 = n_data / 4;
    int cl4 = CL / 4;
    int cl4_shift = 0;
    while ((1 << cl4_shift) < cl4) cl4_shift++;   // CL/4 is power of two here
    int nblocks = (n4 + 4 * 256 - 1) / (4 * 256); // ~4 float4 per thread
    norm_kernel<<<nblocks, 256>>>((const float4*)data, (float4*)out, n4, cl4_shift);

    // 4) tail (idxes + zero_pos), only if harness expects them
    long long extra = (long long)out_size - (long long)n_data;
    if (extra > 0) {
        int t_idx = (int)((extra < (long long)n_idx) ? extra : n_idx);
        long long extra2 = extra - t_idx;
        int t_zp = (int)((extra2 < (long long)B) ? (extra2 > 0 ? extra2 : 0) : B);
        int tot = t_idx + t_zp;
        if (tot > 0) {
            int tb = (tot + 255) / 256;
            tail_kernel<<<tb, 256>>>(idxes, zero_pos, out + n_data, t_idx, t_zp);
        }
    }
}

// round 2
// speedup vs baseline: 1.2340x; 1.2340x over previous
#include <cuda_runtime.h>
#include <math.h>

#define EPS_F 1.1920928955078125e-07f
#define RED_SLICES 16
#define RED_THREADS 256

// scratch (allocation-free rule): partial sums + final stats
__device__ float g_partials[256 * RED_SLICES * 2];  // [b][slice][{sum,sumsq}]
__device__ float g_stats[512];                      // [b][{scale,bias}]

// ---------------------------------------------------------------------------
// Kernel 1: per-batch prefix sum & sumsq partials, row-major, float4 loads.
// grid = (B, RED_SLICES), block = RED_THREADS.
// Block (b, by) handles rows c = by, by+RED_SLICES, ... of batch b.
// ---------------------------------------------------------------------------
__global__ void reduce_kernel(const float* __restrict__ data,
                              const int* __restrict__ zero_pos,
                              int C, int L) {
    int b  = blockIdx.x;
    int zp = zero_pos[b];
    const float* base = data + (size_t)b * C * L;

    int zp4   = zp >> 2;       // full float4s per row
    int zrem  = zp & 3;        // scalar tail per row
    int tid   = threadIdx.x;

    float s = 0.0f, sq = 0.0f;
    for (int c = blockIdx.y; c < C; c += RED_SLICES) {
        const float4* row4 = (const float4*)(base + (size_t)c * L);
        for (int l4 = tid; l4 < zp4; l4 += RED_THREADS) {
            float4 v = row4[l4];
            s  += v.x + v.y + v.z + v.w;
            sq += v.x * v.x + v.y * v.y + v.z * v.z + v.w * v.w;
        }
        if (tid < zrem) {
            float v = base[(size_t)c * L + (zp4 << 2) + tid];
            s  += v;
            sq += v * v;
        }
    }

    // block reduction
    __shared__ float sh_s[RED_THREADS];
    __shared__ float sh_q[RED_THREADS];
    sh_s[tid] = s;
    sh_q[tid] = sq;
    __syncthreads();
    for (int off = RED_THREADS / 2; off >= 32; off >>= 1) {
        if (tid < off) {
            sh_s[tid] += sh_s[tid + off];
            sh_q[tid] += sh_q[tid + off];
        }
        __syncthreads();
    }
    if (tid < 32) {
        float vs = sh_s[tid];
        float vq = sh_q[tid];
        for (int off = 16; off > 0; off >>= 1) {
            vs += __shfl_down_sync(0xFFFFFFFFu, vs, off);
            vq += __shfl_down_sync(0xFFFFFFFFu, vq, off);
        }
        if (tid == 0) {
            int slot = (b * RED_SLICES + blockIdx.y) * 2;
            g_partials[slot + 0] = vs;
            g_partials[slot + 1] = vq;
        }
    }
}

// ---------------------------------------------------------------------------
// Kernel 2: fold partials -> scale = 1/(std+eps), bias = -mean*scale.
// 1 block, B threads.
// ---------------------------------------------------------------------------
__global__ void stats_kernel(const int* __restrict__ zero_pos, int C) {
    int b = threadIdx.x;
    float s = 0.0f, sq = 0.0f;
#pragma unroll
    for (int j = 0; j < RED_SLICES; j++) {
        int slot = (b * RED_SLICES + j) * 2;
        s  += g_partials[slot + 0];
        sq += g_partials[slot + 1];
    }
    float cnt   = (float)C * (float)zero_pos[b];
    float mean  = s / cnt;
    float var   = (sq - cnt * mean * mean) / (cnt - 1.0f);
    float scale = 1.0f / (sqrtf(var) + EPS_F);
    g_stats[2 * b + 0] = scale;
    g_stats[2 * b + 1] = -mean * scale;
}

// ---------------------------------------------------------------------------
// Kernel 3: normalize full tensor + emit tail (idxes, zero_pos cast to float),
// all as one grid-stride float4 pass over out_size/4 slots.
//   i < n4                  : out = fma(data, scale, bias)
//   n4 <= i < n4+nidx4      : out = (float) idxes (int4)
//   else                    : out = (float) zero_pos (int4)
// ---------------------------------------------------------------------------
__global__ void norm_tail_kernel(const float4* __restrict__ data4,
                                 const int4* __restrict__ idxes4,
                                 const int4* __restrict__ zp4,
                                 float4* __restrict__ out4,
                                 int n4, int nidx4, int total4,
                                 int cl4_shift) {
    int stride = gridDim.x * blockDim.x;
    for (int i = blockIdx.x * blockDim.x + threadIdx.x; i < total4; i += stride) {
        float4 o;
        if (i < n4) {
            int b = i >> cl4_shift;
            float scale = g_stats[2 * b + 0];
            float bias  = g_stats[2 * b + 1];
            float4 v = data4[i];
            o.x = fmaf(v.x, scale, bias);
            o.y = fmaf(v.y, scale, bias);
            o.z = fmaf(v.z, scale, bias);
            o.w = fmaf(v.w, scale, bias);
        } else {
            int j = i - n4;
            int4 t = (j < nidx4) ? idxes4[j] : zp4[j - nidx4];
            o.x = (float)t.x;
            o.y = (float)t.y;
            o.z = (float)t.z;
            o.w = (float)t.w;
        }
        out4[i] = o;
    }
}

extern "C" void kernel_launch(void* const* d_in, const int* in_sizes, int n_in,
                              void* d_out, int out_size) {
    const float* data     = (const float*)d_in[0];
    const int*   idxes    = (const int*)d_in[1];
    const int*   zero_pos = (const int*)d_in[2];
    float*       out      = (float*)d_out;

    int n_data = in_sizes[0];            // B*C*L = 33554432
    int n_idx  = in_sizes[1];            // B*L   = 524288
    int B      = in_sizes[2];            // 64
    int CL     = n_data / B;             // 524288
    int L      = n_idx / B;              // 8192
    int C      = CL / L;                 // 64

    // 1) partial reductions over prefixes (row-major, vectorized)
    dim3 g1(B, RED_SLICES);
    reduce_kernel<<<g1, RED_THREADS>>>(data, zero_pos, C, L);

    // 2) stats
    stats_kernel<<<1, B>>>(zero_pos, C);

    // 3) fused normalize + tail
    int n4  = n_data / 4;
    int cl4 = CL / 4;
    int cl4_shift = 0;
    while ((1 << cl4_shift) < cl4) cl4_shift++;   // CL/4 power of two

    int total  = (out_size > n_data) ? out_size : n_data;
    int total4 = total / 4;                       // out_size divisible by 4
    int nidx4  = n_idx / 4;

    int nblocks = (total4 + 4 * 256 - 1) / (4 * 256);  // ~4 float4 per thread
    norm_tail_kernel<<<nblocks, 256>>>((const float4*)data,
                                       (const int4*)idxes,
                                       (const int4*)zero_pos,
                                       (float4*)out,
                                       n4, nidx4, total4, cl4_shift);
}

// round 3
// speedup vs baseline: 1.2680x; 1.0275x over previous
#include <cuda_runtime.h>
#include <math.h>

#define EPS_F 1.1920928955078125e-07f
#define RED_THREADS 256
#define MAX_C 64

// scratch (allocation-free rule): partial sums + final stats
__device__ float g_partials[256 * MAX_C * 2];  // [b][c][{sum,sumsq}]
__device__ float g_stats[512];                 // [b][{scale,bias}]

// ---------------------------------------------------------------------------
// Kernel 1: per-(batch,row) prefix sum & sumsq. grid = (B, C), one row/block.
// Fine granularity (<=32KB per block) so the scheduler load-balances ragged zp.
// ---------------------------------------------------------------------------
__global__ void reduce_kernel(const float* __restrict__ data,
                              const int* __restrict__ zero_pos,
                              int C, int L) {
    int b  = blockIdx.x;
    int c  = blockIdx.y;
    int zp = zero_pos[b];

    const float* row = data + ((size_t)b * C + c) * L;
    int zp4  = zp >> 2;
    int zrem = zp & 3;
    int tid  = threadIdx.x;

    float s = 0.0f, sq = 0.0f;
    const float4* row4 = (const float4*)row;
    for (int l4 = tid; l4 < zp4; l4 += RED_THREADS) {
        float4 v = row4[l4];
        s  += v.x + v.y + v.z + v.w;
        sq += v.x * v.x + v.y * v.y + v.z * v.z + v.w * v.w;
    }
    if (tid < zrem) {
        float v = row[(zp4 << 2) + tid];
        s  += v;
        sq += v * v;
    }

    // block reduction
    __shared__ float sh_s[RED_THREADS];
    __shared__ float sh_q[RED_THREADS];
    sh_s[tid] = s;
    sh_q[tid] = sq;
    __syncthreads();
    for (int off = RED_THREADS / 2; off >= 32; off >>= 1) {
        if (tid < off) {
            sh_s[tid] += sh_s[tid + off];
            sh_q[tid] += sh_q[tid + off];
        }
        __syncthreads();
    }
    if (tid < 32) {
        float vs = sh_s[tid];
        float vq = sh_q[tid];
        for (int off = 16; off > 0; off >>= 1) {
            vs += __shfl_down_sync(0xFFFFFFFFu, vs, off);
            vq += __shfl_down_sync(0xFFFFFFFFu, vq, off);
        }
        if (tid == 0) {
            int slot = (b * MAX_C + c) * 2;
            g_partials[slot + 0] = vs;
            g_partials[slot + 1] = vq;
        }
    }
}

// ---------------------------------------------------------------------------
// Kernel 2: fold partials -> scale = 1/(std+eps), bias = -mean*scale.
// 1 block, B threads; deterministic (fixed summation order).
// ---------------------------------------------------------------------------
__global__ void stats_kernel(const int* __restrict__ zero_pos, int C) {
    int b = threadIdx.x;
    float s = 0.0f, sq = 0.0f;
    for (int j = 0; j < C; j++) {
        int slot = (b * MAX_C + j) * 2;
        s  += g_partials[slot + 0];
        sq += g_partials[slot + 1];
    }
    float cnt   = (float)C * (float)zero_pos[b];
    float mean  = s / cnt;
    float var   = (sq - cnt * mean * mean) / (cnt - 1.0f);
    float scale = 1.0f / (sqrtf(var) + EPS_F);
    g_stats[2 * b + 0] = scale;
    g_stats[2 * b + 1] = -mean * scale;
}

// ---------------------------------------------------------------------------
// Kernel 3: normalize full tensor + emit tail (idxes, zero_pos cast to float),
// one grid-stride float4 pass over out_size/4 slots.
// ---------------------------------------------------------------------------
__global__ void norm_tail_kernel(const float4* __restrict__ data4,
                                 const int4* __restrict__ idxes4,
                                 const int4* __restrict__ zp4,
                                 float4* __restrict__ out4,
                                 int n4, int nidx4, int total4,
                                 int cl4_shift) {
    int stride = gridDim.x * blockDim.x;
    for (int i = blockIdx.x * blockDim.x + threadIdx.x; i < total4; i += stride) {
        float4 o;
        if (i < n4) {
            int b = i >> cl4_shift;
            float scale = g_stats[2 * b + 0];
            float bias  = g_stats[2 * b + 1];
            float4 v = data4[i];
            o.x = fmaf(v.x, scale, bias);
            o.y = fmaf(v.y, scale, bias);
            o.z = fmaf(v.z, scale, bias);
            o.w = fmaf(v.w, scale, bias);
        } else {
            int j = i - n4;
            int4 t = (j < nidx4) ? idxes4[j] : zp4[j - nidx4];
            o.x = (float)t.x;
            o.y = (float)t.y;
            o.z = (float)t.z;
            o.w = (float)t.w;
        }
        out4[i] = o;
    }
}

extern "C" void kernel_launch(void* const* d_in, const int* in_sizes, int n_in,
                              void* d_out, int out_size) {
    const float* data     = (const float*)d_in[0];
    const int*   idxes    = (const int*)d_in[1];
    const int*   zero_pos = (const int*)d_in[2];
    float*       out      = (float*)d_out;

    int n_data = in_sizes[0];            // B*C*L = 33554432
    int n_idx  = in_sizes[1];            // B*L   = 524288
    int B      = in_sizes[2];            // 64
    int CL     = n_data / B;             // 524288
    int L      = n_idx / B;              // 8192
    int C      = CL / L;                 // 64

    // 1) partial reductions over prefixes: one row per block
    dim3 g1(B, C);
    reduce_kernel<<<g1, RED_THREADS>>>(data, zero_pos, C, L);

    // 2) stats
    stats_kernel<<<1, B>>>(zero_pos, C);

    // 3) fused normalize + tail
    int n4  = n_data / 4;
    int cl4 = CL / 4;
    int cl4_shift = 0;
    while ((1 << cl4_shift) < cl4) cl4_shift++;   // CL/4 power of two

    int total  = (out_size > n_data) ? out_size : n_data;
    int total4 = total / 4;
    int nidx4  = n_idx / 4;

    int nblocks = (total4 + 4 * 256 - 1) / (4 * 256);  // ~4 float4 per thread
    norm_tail_kernel<<<nblocks, 256>>>((const float4*)data,
                                       (const int4*)idxes,
                                       (const int4*)zero_pos,
                                       (float4*)out,
                                       n4, nidx4, total4, cl4_shift);
}

// round 6
// speedup vs baseline: 1.3571x; 1.0703x over previous
#include <cuda_runtime.h>
#include <math.h>

#define EPS_F 1.1920928955078125e-07f
#define RED_THREADS 256
#define MAX_C 64

// scratch (allocation-free rule): partial sums + final stats
__device__ float g_partials[256 * MAX_C * 2];  // [b][c][{sum,sumsq}]
__device__ float g_stats[512];                 // [b][{scale,bias}]

// ---------------------------------------------------------------------------
// Kernel 1: per-(batch,row) prefix sum & sumsq. grid = (B, C), one row/block.
// Row length zp <= 8192 -> zp4 <= 2048 = 8 * 256: fully-unrolled predicated
// 8-load body per thread gives MLP=8 to cover DRAM latency.
// ---------------------------------------------------------------------------
__global__ void reduce_kernel(const float* __restrict__ data,
                              const int* __restrict__ zero_pos,
                              int C, int L) {
    int b  = blockIdx.x;
    int c  = blockIdx.y;
    int zp = zero_pos[b];

    const float* row = data + ((size_t)b * C + c) * L;
    int zp4  = zp >> 2;
    int zrem = zp & 3;
    int tid  = threadIdx.x;

    const float4* row4 = (const float4*)row;

    float4 v[8];
    int    valid[8];
#pragma unroll
    for (int k = 0; k < 8; k++) {
        int idx  = tid + k * RED_THREADS;
        valid[k] = (idx < zp4);
        if (valid[k]) v[k] = row4[idx];           // 8 independent loads in flight
    }

    float s0 = 0.f, q0 = 0.f, s1 = 0.f, q1 = 0.f;
#pragma unroll
    for (int k = 0; k < 8; k += 2) {
        if (valid[k]) {
            s0 += v[k].x + v[k].y + v[k].z + v[k].w;
            q0 += v[k].x * v[k].x + v[k].y * v[k].y + v[k].z * v[k].z + v[k].w * v[k].w;
        }
        if (valid[k + 1]) {
            s1 += v[k+1].x + v[k+1].y + v[k+1].z + v[k+1].w;
            q1 += v[k+1].x * v[k+1].x + v[k+1].y * v[k+1].y + v[k+1].z * v[k+1].z + v[k+1].w * v[k+1].w;
        }
    }
    float s = s0 + s1, sq = q0 + q1;

    if (tid < zrem) {
        float x = row[(zp4 << 2) + tid];
        s  += x;
        sq += x * x;
    }

    // block reduction
    __shared__ float sh_s[RED_THREADS];
    __shared__ float sh_q[RED_THREADS];
    sh_s[tid] = s;
    sh_q[tid] = sq;
    __syncthreads();
    for (int off = RED_THREADS / 2; off >= 32; off >>= 1) {
        if (tid < off) {
            sh_s[tid] += sh_s[tid + off];
            sh_q[tid] += sh_q[tid + off];
        }
        __syncthreads();
    }
    if (tid < 32) {
        float vs = sh_s[tid];
        float vq = sh_q[tid];
        for (int off = 16; off > 0; off >>= 1) {
            vs += __shfl_down_sync(0xFFFFFFFFu, vs, off);
            vq += __shfl_down_sync(0xFFFFFFFFu, vq, off);
        }
        if (tid == 0) {
            int slot = (b * MAX_C + c) * 2;
            g_partials[slot + 0] = vs;
            g_partials[slot + 1] = vq;
        }
    }
}

// ---------------------------------------------------------------------------
// Kernel 2: fold partials -> scale = 1/(std+eps), bias = -mean*scale.
// 1 block, B threads; deterministic (fixed summation order).
// ---------------------------------------------------------------------------
__global__ void stats_kernel(const int* __restrict__ zero_pos, int C) {
    int b = threadIdx.x;
    float s = 0.0f, sq = 0.0f;
    for (int j = 0; j < C; j++) {
        int slot = (b * MAX_C + j) * 2;
        s  += g_partials[slot + 0];
        sq += g_partials[slot + 1];
    }
    float cnt   = (float)C * (float)zero_pos[b];
    float mean  = s / cnt;
    float var   = (sq - cnt * mean * mean) / (cnt - 1.0f);
    float scale = 1.0f / (sqrtf(var) + EPS_F);
    g_stats[2 * b + 0] = scale;
    g_stats[2 * b + 1] = -mean * scale;
}

// ---------------------------------------------------------------------------
// Kernel 3: normalize full tensor + emit tail (idxes, zero_pos cast to float).
// Streaming loads/stores (__ldcs/__stcs): none of this data is re-read.
// ---------------------------------------------------------------------------
__global__ void norm_tail_kernel(const float4* __restrict__ data4,
                                 const int4* __restrict__ idxes4,
                                 const int4* __restrict__ zp4,
                                 float4* __restrict__ out4,
                                 int n4, int nidx4, int total4,
                                 int cl4_shift) {
    int stride = gridDim.x * blockDim.x;
    for (int i = blockIdx.x * blockDim.x + threadIdx.x; i < total4; i += stride) {
        float4 o;
        if (i < n4) {
            int b = i >> cl4_shift;
            float scale = g_stats[2 * b + 0];
            float bias  = g_stats[2 * b + 1];
            float4 v = __ldcs(data4 + i);
            o.x = fmaf(v.x, scale, bias);
            o.y = fmaf(v.y, scale, bias);
            o.z = fmaf(v.z, scale, bias);
            o.w = fmaf(v.w, scale, bias);
        } else {
            int j = i - n4;
            int4 t = (j < nidx4) ? __ldcs(idxes4 + j) : __ldcs(zp4 + (j - nidx4));
            o.x = (float)t.x;
            o.y = (float)t.y;
            o.z = (float)t.z;
            o.w = (float)t.w;
        }
        __stcs(out4 + i, o);
    }
}

extern "C" void kernel_launch(void* const* d_in, const int* in_sizes, int n_in,
                              void* d_out, int out_size) {
    const float* data     = (const float*)d_in[0];
    const int*   idxes    = (const int*)d_in[1];
    const int*   zero_pos = (const int*)d_in[2];
    float*       out      = (float*)d_out;

    int n_data = in_sizes[0];            // B*C*L = 33554432
    int n_idx  = in_sizes[1];            // B*L   = 524288
    int B      = in_sizes[2];            // 64
    int CL     = n_data / B;             // 524288
    int L      = n_idx / B;              // 8192
    int C      = CL / L;                 // 64

    // 1) partial reductions over prefixes: one row per block, MLP=8
    dim3 g1(B, C);
    reduce_kernel<<<g1, RED_THREADS>>>(data, zero_pos, C, L);

    // 2) stats
    stats_kernel<<<1, B>>>(zero_pos, C);

    // 3) fused normalize + tail
    int n4  = n_data / 4;
    int cl4 = CL / 4;
    int cl4_shift = 0;
    while ((1 << cl4_shift) < cl4) cl4_shift++;   // CL/4 power of two

    int total  = (out_size > n_data) ? out_size : n_data;
    int total4 = total / 4;
    int nidx4  = n_idx / 4;

    int nblocks = (total4 + 4 * 256 - 1) / (4 * 256);  // ~4 float4 per thread
    norm_tail_kernel<<<nblocks, 256>>>((const float4*)data,
                                       (const int4*)idxes,
                                       (const int4*)zero_pos,
                                       (float4*)out,
                                       n4, nidx4, total4, cl4_shift);
}